// round 15
// baseline (speedup 1.0000x reference)
#include <cuda_runtime.h>
#include <cuda_fp16.h>
#include <cstdint>

#define LDIM 2048
#define BDIM 32
#define DDIM 512
#define MDIM (LDIM * BDIM)   // 65536
#define NDIM (DDIM * 3)      // 1536
#define KDIM DDIM            // 512

#define BM 128
#define BN 96
#define BK 64
#define NCHUNK (KDIM / BK)   // 8
#define NTILES_N 16
#define NTILES_M 512
#define TOT_TILES (NTILES_M * NTILES_N)   // 8192
#define NCTAS 296

// ---------------------------------------------------------------------------
// Device scratch
// ---------------------------------------------------------------------------
__device__ uint2  g_U8[(size_t)MDIM * DDIM];   // {fp32 u0, half u1, half u2}, 256 MB
__device__ __half g_Ah[(size_t)MDIM * KDIM];   // x fp16
__device__ __half g_Bh[(size_t)NDIM * KDIM];   // W^T fp16 [o][k]
__device__ int    g_cnt[NTILES_M];             // per-m-tile completion counters

__device__ __forceinline__ uint32_t smem_u32(const void* p) {
    uint32_t a;
    asm("{ .reg .u64 t; cvta.to.shared.u64 t, %1; cvt.u32.u64 %0, t; }" : "=r"(a) : "l"(p));
    return a;
}
#define SW128(o) ((o) ^ (((o) >> 3) & 0x70))

__device__ __forceinline__ void cp_async16(uint32_t saddr, const void* gaddr) {
    asm volatile("cp.async.cg.shared.global [%0], [%1], 16;" :: "r"(saddr), "l"(gaddr) : "memory");
}
__device__ __forceinline__ void cp_async8(uint32_t saddr, const void* gaddr) {
    asm volatile("cp.async.ca.shared.global [%0], [%1], 8;" :: "r"(saddr), "l"(gaddr) : "memory");
}
__device__ __forceinline__ void cp_async4(uint32_t saddr, const void* gaddr) {
    asm volatile("cp.async.ca.shared.global [%0], [%1], 4;" :: "r"(saddr), "l"(gaddr) : "memory");
}
#define CP_COMMIT() asm volatile("cp.async.commit_group;" ::: "memory")
#define CP_WAIT(n)  asm volatile("cp.async.wait_group %0;" :: "n"(n) : "memory")
#define BARG()      asm volatile("bar.sync 1, 192;" ::: "memory")

__device__ __forceinline__ void ldsm_x4(uint32_t& r0, uint32_t& r1, uint32_t& r2, uint32_t& r3, uint32_t addr) {
    asm volatile("ldmatrix.sync.aligned.m8n8.x4.shared.b16 {%0,%1,%2,%3}, [%4];"
                 : "=r"(r0), "=r"(r1), "=r"(r2), "=r"(r3) : "r"(addr));
}
__device__ __forceinline__ void mma_f16(float& c0, float& c1, float& c2, float& c3,
                                        uint32_t a0, uint32_t a1, uint32_t a2, uint32_t a3,
                                        uint32_t b0, uint32_t b1) {
    asm volatile("mma.sync.aligned.m16n8k16.row.col.f32.f16.f16.f32 "
                 "{%0,%1,%2,%3}, {%4,%5,%6,%7}, {%8,%9}, {%0,%1,%2,%3};"
                 : "+f"(c0), "+f"(c1), "+f"(c2), "+f"(c3)
                 : "r"(a0), "r"(a1), "r"(a2), "r"(a3), "r"(b0), "r"(b1));
}
__device__ __forceinline__ float ex2f(float z) { float r; asm("ex2.approx.f32 %0, %1;" : "=f"(r) : "f"(z)); return r; }
__device__ __forceinline__ float rcpf(float z) { float r; asm("rcp.approx.f32 %0, %1;" : "=f"(r) : "f"(z)); return r; }

__device__ __forceinline__ int ld_cnt(const int* p) {
    int v;
    asm volatile("ld.global.cg.b32 %0, [%1];" : "=r"(v) : "l"(p));
    return v;
}

// ---------------------------------------------------------------------------
// Converts fused (also resets g_cnt)
// ---------------------------------------------------------------------------
__global__ __launch_bounds__(256)
void convert_all_kernel(const float* __restrict__ x, const float* __restrict__ W)
{
    const size_t i = (size_t)blockIdx.x * 256 + threadIdx.x;
    const float4 v0 = ((const float4*)x)[2 * i];
    const float4 v1 = ((const float4*)x)[2 * i + 1];
    __half2 h[4];
    h[0] = __floats2half2_rn(v0.x, v0.y);
    h[1] = __floats2half2_rn(v0.z, v0.w);
    h[2] = __floats2half2_rn(v1.x, v1.y);
    h[3] = __floats2half2_rn(v1.z, v1.w);
    ((uint4*)g_Ah)[i] = *(const uint4*)h;

    const int idx = blockIdx.x * 256 + threadIdx.x;
    if (idx < KDIM * NDIM) {
        const int k = idx / NDIM;
        const int o = idx % NDIM;
        g_Bh[(size_t)o * KDIM + k] = __float2half_rn(W[idx]);
    }
    if (blockIdx.x == 0 && threadIdx.x < 256) {
        g_cnt[threadIdx.x] = 0;
        g_cnt[threadIdx.x + 256] = 0;
    }
}

// ---------------------------------------------------------------------------
// Fused producer-consumer kernel, 2 CTAs/SM.
//   warps 0-5 (tid<192): persistent HMMA GEMM, 128x96 tiles, BK=64, 2-stage
//   warps 6-7 (tid>=192, CTAs 0..127): SRU scan, 2 channels/thread
// ---------------------------------------------------------------------------
#define ABUF_B (BM * BK * 2)        // 16384
#define BBUF_B (BN * BK * 2)        // 12288
#define STAGE_B (ABUF_B + BBUF_B)   // 28672
#define GSMEM (2 * STAGE_B)         // 57344 dynamic
#define EP_P 100
#define SSTG 16                     // scan ring (steps)

__global__ __launch_bounds__(256, 2)
void sru_fused(const float* __restrict__ x,
               const float* __restrict__ wc,
               const float* __restrict__ bias,
               float* __restrict__ out)
{
    extern __shared__ char smem[];
    __shared__ uint2 s_ru[SSTG][128];   // 16 KB static
    __shared__ float s_rx[SSTG][128];   // 8 KB static

    const uint32_t sbase = smem_u32(smem);
    const int tid = threadIdx.x;
    const int bx = blockIdx.x;

    if (tid < 192) {
        // ================= GEMM producer (6 warps) =================
        const int wid = tid >> 5;
        const int lane = tid & 31;
        const int wmh = wid & 1;            // m half
        const int wm0 = wmh * 64;
        const int wn0 = (wid >> 1) * 32;    // n third of 96

        const int myT = (TOT_TILES - bx + NCTAS - 1) / NCTAS;
        const int totq = myT * NCHUNK;

        auto issue = [&](int q) {
            if (q >= totq) return;
            const int tile = bx + (q >> 3) * NCTAS;
            const int c = q & 7;
            const int m0 = (tile >> 4) * BM;
            const int n0 = (tile & 15) * BN;
            const int k0 = c * BK;
            const uint32_t sb = sbase + (uint32_t)((q & 1) * STAGE_B);
            const __half* srcA = g_Ah + (size_t)m0 * KDIM + k0;
            const __half* srcB = g_Bh + (size_t)n0 * KDIM + k0;
#pragma unroll
            for (int j = 0; j < 6; ++j) {               // A: 1024 uint4
                const int slot = j * 192 + tid;
                if (slot < 1024) {
                    const int row  = slot >> 3;
                    const int kb   = slot & 7;
                    cp_async16(sb + SW128(row * 128 + kb * 16), srcA + (size_t)row * KDIM + kb * 8);
                }
            }
#pragma unroll
            for (int j = 0; j < 4; ++j) {               // B: 768 uint4
                const int slot = j * 192 + tid;
                const int row  = slot >> 3;
                const int kb   = slot & 7;
                cp_async16(sb + ABUF_B + SW128(row * 128 + kb * 16), srcB + (size_t)row * KDIM + kb * 8);
            }
        };

        float acc[4][4][4];                 // 64 regs
#pragma unroll
        for (int i = 0; i < 4; i++)
#pragma unroll
            for (int j = 0; j < 4; j++)
#pragma unroll
                for (int q = 0; q < 4; q++) acc[i][j][q] = 0.f;

        issue(0); CP_COMMIT();

        for (int q = 0; q < totq; ++q) {
            issue(q + 1); CP_COMMIT();
            CP_WAIT(1);
            BARG();

            const uint32_t sb = sbase + (uint32_t)((q & 1) * STAGE_B);
            const uint32_t sA = sb;
            const uint32_t sB = sb + ABUF_B;

#pragma unroll
            for (int s = 0; s < 4; ++s) {   // four k16 steps
                uint32_t ah[4][4];
                {
                    const int arow = (lane & 15);
                    const int akb  = 2 * s + (lane >> 4);
#pragma unroll
                    for (int mf = 0; mf < 4; ++mf) {
                        const uint32_t off = SW128((uint32_t)(wm0 + mf * 16 + arow) * 128 + akb * 16);
                        ldsm_x4(ah[mf][0], ah[mf][1], ah[mf][2], ah[mf][3], sA + off);
                    }
                }
                uint32_t bh[4][2];
                {
                    const int brow = (lane & 7) + ((lane >> 4) & 1) * 8;
                    const int bkb  = 2 * s + ((lane >> 3) & 1);
#pragma unroll
                    for (int nf16 = 0; nf16 < 2; ++nf16) {
                        const uint32_t off = SW128((uint32_t)(wn0 + nf16 * 16 + brow) * 128 + bkb * 16);
                        ldsm_x4(bh[nf16*2][0], bh[nf16*2][1], bh[nf16*2+1][0], bh[nf16*2+1][1], sB + off);
                    }
                }
#pragma unroll
                for (int mf = 0; mf < 4; ++mf)
#pragma unroll
                    for (int nf = 0; nf < 4; ++nf) {
                        float* C = acc[mf][nf];
                        mma_f16(C[0], C[1], C[2], C[3],
                                ah[mf][0], ah[mf][1], ah[mf][2], ah[mf][3],
                                bh[nf][0], bh[nf][1]);
                    }
            }
            BARG();

            if ((q & 7) == 7) {
                const int tile = bx + (q >> 3) * NCTAS;
                const int m0 = (tile >> 4) * BM;
                const int d0 = (tile & 15) * 32;
                float* ep = (float*)(smem + (size_t)((q & 1) * STAGE_B));

#pragma unroll
                for (int q2 = 0; q2 < 4; ++q2) {        // quarters of 32 rows
                    if (wmh == (q2 >> 1)) {
                        const int g = lane >> 2;
                        const int t4 = lane & 3;
#pragma unroll
                        for (int e = 0; e < 2; ++e) {
                            const int mf = 2 * (q2 & 1) + e;
                            const int lr = e * 16 + g;  // 0..31 within quarter
#pragma unroll
                            for (int nf = 0; nf < 4; ++nf) {
                                const int col = wn0 + nf * 8 + 2 * t4;
                                float* C = acc[mf][nf];
                                ep[lr * EP_P + col]           = C[0];
                                ep[lr * EP_P + col + 1]       = C[1];
                                ep[(lr + 8) * EP_P + col]     = C[2];
                                ep[(lr + 8) * EP_P + col + 1] = C[3];
                            }
                        }
                    }
                    BARG();
#pragma unroll
                    for (int it = 0; it < 6; ++it) {    // 1024 words, 192 thr
                        const int lin = it * 192 + tid;
                        if (lin < 1024) {
                            const int lr = lin >> 5;
                            const int dc = lin & 31;
                            const float u0 = ep[lr * EP_P + 3 * dc];
                            const float u1 = ep[lr * EP_P + 3 * dc + 1];
                            const float u2 = ep[lr * EP_P + 3 * dc + 2];
                            uint2 w;
                            w.x = __float_as_uint(u0);
                            const __half2 p = __floats2half2_rn(u1, u2);
                            w.y = *(const uint32_t*)&p;
                            g_U8[(size_t)(m0 + q2 * 32 + lr) * DDIM + d0 + dc] = w;
                        }
                    }
                    BARG();
                }

                __threadfence();
                BARG();
                if (tid == 0) atomicAdd(&g_cnt[tile >> 4], 1);

#pragma unroll
                for (int i = 0; i < 4; i++)
#pragma unroll
                    for (int j = 0; j < 4; j++)
#pragma unroll
                        for (int p = 0; p < 4; p++) acc[i][j][p] = 0.f;
            }
        }
    } else {
        // ================= scan consumer (2 warps, 2 channels/thread) ======
        if (bx >= 128) return;
        const int st = tid - 192;                 // 0..63
        const int ch0 = bx * 128 + st;
        const int ch1 = ch0 + 64;
        const int d0 = ch0 & (DDIM - 1);
        const int d1 = ch1 & (DDIM - 1);

        const float LOG2E = 1.4426950408889634f;
        const float wcf0 = -wc[d0] * LOG2E,          wcf1 = -wc[d1] * LOG2E;
        const float wcr0 = -wc[DDIM + d0] * LOG2E,   wcr1 = -wc[DDIM + d1] * LOG2E;
        const float bf0 = -bias[d0] * LOG2E,         bf1 = -bias[d1] * LOG2E;
        const float br0 = -bias[DDIM + d0] * LOG2E,  br1 = -bias[DDIM + d1] * LOG2E;

        const uint32_t ru_base = smem_u32(&s_ru[0][0]);
        const uint32_t rx_base = smem_u32(&s_rx[0][0]);
        const size_t stride = (size_t)BDIM * DDIM;      // 16384

        auto wait_tile = [&](int mt) {
            while (ld_cnt(&g_cnt[mt]) < NTILES_N) __nanosleep(64);
        };
        auto prefetch = [&](int l) {
            const int slot = l & (SSTG - 1);
            cp_async8(ru_base + (uint32_t)(slot * 128 + st) * 8,
                      g_U8 + (size_t)l * stride + ch0);
            cp_async8(ru_base + (uint32_t)(slot * 128 + st + 64) * 8,
                      g_U8 + (size_t)l * stride + ch1);
            cp_async4(rx_base + (uint32_t)(slot * 128 + st) * 4,
                      x + (size_t)l * stride + ch0);
            cp_async4(rx_base + (uint32_t)(slot * 128 + st + 64) * 4,
                      x + (size_t)l * stride + ch1);
        };

#pragma unroll
        for (int g = 0; g < 4; ++g) {
            wait_tile(g);
#pragma unroll
            for (int i = 0; i < 4; ++i) prefetch(g * 4 + i);
            CP_COMMIT();
        }

        float c0 = 0.f, c1 = 0.f;
        for (int gi = 0; gi < LDIM / 4; ++gi) {
            CP_WAIT(3);
#pragma unroll
            for (int i = 0; i < 4; ++i) {
                const int l = gi * 4 + i;
                const int slot = l & (SSTG - 1);
                const uint2 w0 = s_ru[slot][st];
                const uint2 w1 = s_ru[slot][st + 64];
                const float xv0 = s_rx[slot][st];
                const float xv1 = s_rx[slot][st + 64];

                const float u00 = __uint_as_float(w0.x);
                const float2 u12a = __half22float2(*(const __half2*)&w0.y);
                const float fg0 = rcpf(1.f + ex2f(fmaf(wcf0, c0, fmaf(-LOG2E, u12a.x, bf0))));
                const float rg0 = rcpf(1.f + ex2f(fmaf(wcr0, c0, fmaf(-LOG2E, u12a.y, br0))));
                c0 = fmaf(fg0, c0 - u00, u00);
                const float h0 = fmaf(rg0, c0 - xv0, xv0);

                const float u01 = __uint_as_float(w1.x);
                const float2 u12b = __half22float2(*(const __half2*)&w1.y);
                const float fg1 = rcpf(1.f + ex2f(fmaf(wcf1, c1, fmaf(-LOG2E, u12b.x, bf1))));
                const float rg1 = rcpf(1.f + ex2f(fmaf(wcr1, c1, fmaf(-LOG2E, u12b.y, br1))));
                c1 = fmaf(fg1, c1 - u01, u01);
                const float h1 = fmaf(rg1, c1 - xv1, xv1);

                out[(size_t)l * stride + ch0] = h0;
                out[(size_t)l * stride + ch1] = h1;
            }
            const int ng = gi + 4;
            if (ng < LDIM / 4) {
                wait_tile(ng);
#pragma unroll
                for (int i = 0; i < 4; ++i) prefetch(ng * 4 + i);
            }
            CP_COMMIT();
        }

        out[(size_t)LDIM * stride + ch0] = c0;
        out[(size_t)LDIM * stride + ch1] = c1;
    }
}

// ---------------------------------------------------------------------------
extern "C" void kernel_launch(void* const* d_in, const int* in_sizes, int n_in,
                              void* d_out, int out_size)
{
    const float* x    = (const float*)d_in[0];   // (L,B,D)
    const float* W    = (const float*)d_in[1];   // (D, 3D)
    const float* wc   = (const float*)d_in[2];   // (2D,)
    const float* bias = (const float*)d_in[3];   // (2D,)
    float* out = (float*)d_out;

    cudaFuncSetAttribute(sru_fused, cudaFuncAttributeMaxDynamicSharedMemorySize, GSMEM);

    convert_all_kernel<<<(MDIM * KDIM / 8) / 256, 256>>>(x, W);   // also resets g_cnt

    sru_fused<<<NCTAS, 256, GSMEM>>>(x, wc, bias, out);
}

// round 16
// speedup vs baseline: 1.1303x; 1.1303x over previous
#include <cuda_runtime.h>
#include <cuda_fp16.h>
#include <cstdint>

#define LDIM 2048
#define BDIM 32
#define DDIM 512
#define MDIM (LDIM * BDIM)   // 65536
#define NDIM (DDIM * 3)      // 1536
#define KDIM DDIM            // 512

#define BM 128
#define BN 192
#define BK 128
#define NCHUNK (KDIM / BK)   // 4
#define NTILES_N 8
#define NTILES_M 512
#define TOT_TILES (NTILES_M * NTILES_N)   // 4096
#define NGEMM_CTAS 152       // GB300: 152 SMs

// ---------------------------------------------------------------------------
// Device scratch
// ---------------------------------------------------------------------------
__device__ uint2  g_U8[(size_t)MDIM * DDIM];   // {fp32 u0, half u1, half u2}, 256 MB
__device__ __half g_Ah[(size_t)MDIM * KDIM];   // x fp16
__device__ __half g_Bh[(size_t)NDIM * KDIM];   // W^T fp16 [o][k]
__device__ int    g_cnt[NTILES_M];             // per-m-tile completion counters

__device__ __forceinline__ uint32_t smem_u32(const void* p) {
    uint32_t a;
    asm("{ .reg .u64 t; cvta.to.shared.u64 t, %1; cvt.u32.u64 %0, t; }" : "=r"(a) : "l"(p));
    return a;
}
#define SW128(o) ((o) ^ (((o) >> 3) & 0x70))

__device__ __forceinline__ void cp_async16(uint32_t saddr, const void* gaddr) {
    asm volatile("cp.async.cg.shared.global [%0], [%1], 16;" :: "r"(saddr), "l"(gaddr) : "memory");
}
__device__ __forceinline__ void cp_async8(uint32_t saddr, const void* gaddr) {
    asm volatile("cp.async.ca.shared.global [%0], [%1], 8;" :: "r"(saddr), "l"(gaddr) : "memory");
}
__device__ __forceinline__ void cp_async4(uint32_t saddr, const void* gaddr) {
    asm volatile("cp.async.ca.shared.global [%0], [%1], 4;" :: "r"(saddr), "l"(gaddr) : "memory");
}
#define CP_COMMIT() asm volatile("cp.async.commit_group;" ::: "memory")
#define CP_WAIT(n)  asm volatile("cp.async.wait_group %0;" :: "n"(n) : "memory")
#define BARG()      asm volatile("bar.sync 1, 256;" ::: "memory")

__device__ __forceinline__ void ldsm_x4(uint32_t& r0, uint32_t& r1, uint32_t& r2, uint32_t& r3, uint32_t addr) {
    asm volatile("ldmatrix.sync.aligned.m8n8.x4.shared.b16 {%0,%1,%2,%3}, [%4];"
                 : "=r"(r0), "=r"(r1), "=r"(r2), "=r"(r3) : "r"(addr));
}
__device__ __forceinline__ void mma_f16(float& c0, float& c1, float& c2, float& c3,
                                        uint32_t a0, uint32_t a1, uint32_t a2, uint32_t a3,
                                        uint32_t b0, uint32_t b1) {
    asm volatile("mma.sync.aligned.m16n8k16.row.col.f32.f16.f16.f32 "
                 "{%0,%1,%2,%3}, {%4,%5,%6,%7}, {%8,%9}, {%0,%1,%2,%3};"
                 : "+f"(c0), "+f"(c1), "+f"(c2), "+f"(c3)
                 : "r"(a0), "r"(a1), "r"(a2), "r"(a3), "r"(b0), "r"(b1));
}
__device__ __forceinline__ float ex2f(float z) { float r; asm("ex2.approx.f32 %0, %1;" : "=f"(r) : "f"(z)); return r; }
__device__ __forceinline__ float rcpf(float z) { float r; asm("rcp.approx.f32 %0, %1;" : "=f"(r) : "f"(z)); return r; }

__device__ __forceinline__ int ld_cnt(const int* p) {
    int v;
    asm volatile("ld.global.cg.b32 %0, [%1];" : "=r"(v) : "l"(p));
    return v;
}

// ---------------------------------------------------------------------------
// Converts fused (also resets g_cnt)
// ---------------------------------------------------------------------------
__global__ __launch_bounds__(256)
void convert_all_kernel(const float* __restrict__ x, const float* __restrict__ W)
{
    const size_t i = (size_t)blockIdx.x * 256 + threadIdx.x;
    const float4 v0 = ((const float4*)x)[2 * i];
    const float4 v1 = ((const float4*)x)[2 * i + 1];
    __half2 h[4];
    h[0] = __floats2half2_rn(v0.x, v0.y);
    h[1] = __floats2half2_rn(v0.z, v0.w);
    h[2] = __floats2half2_rn(v1.x, v1.y);
    h[3] = __floats2half2_rn(v1.z, v1.w);
    ((uint4*)g_Ah)[i] = *(const uint4*)h;

    const int idx = blockIdx.x * 256 + threadIdx.x;
    if (idx < KDIM * NDIM) {
        const int k = idx / NDIM;
        const int o = idx % NDIM;
        g_Bh[(size_t)o * KDIM + k] = __float2half_rn(W[idx]);
    }
    if (blockIdx.x == 0 && threadIdx.x < 256) {
        g_cnt[threadIdx.x] = 0;
        g_cnt[threadIdx.x + 256] = 0;
    }
}

// ---------------------------------------------------------------------------
// Fused producer-consumer kernel (R11 shape).
//   warps 0-7 (tid<256): persistent HMMA GEMM, BK=128 chunks, 2-stage pipeline
//   warps 8-11 (tid>=256, CTAs 0..127): SRU scan, 1 channel/thread
// ---------------------------------------------------------------------------
#define ASUB_B (BM * 64 * 2)        // 16384 (one 64-half k sub-tile of A)
#define ABUF_B (2 * ASUB_B)         // 32768
#define BSUB_B (BN * 64 * 2)        // 24576
#define BBUF_B (2 * BSUB_B)         // 49152
#define STAGE_B (ABUF_B + BBUF_B)   // 81920
#define GSMEM (2 * STAGE_B)         // 163840
#define EP_P 196
#define SSTG 16                     // scan ring (steps)

__global__ __launch_bounds__(384, 1)
void sru_fused(const float* __restrict__ x,
               const float* __restrict__ wc,
               const float* __restrict__ bias,
               float* __restrict__ out)
{
    extern __shared__ char smem[];
    __shared__ uint2 s_ru[SSTG][128];
    __shared__ float s_rx[SSTG][128];

    const uint32_t sbase = smem_u32(smem);
    const int tid = threadIdx.x;
    const int bx = blockIdx.x;

    if (tid < 256) {
        // ================= GEMM producer =================
        const int wid = tid >> 5;
        const int lane = tid & 31;
        const int wmh = wid & 1;
        const int wm0 = wmh * 64;
        const int wn0 = (wid >> 1) * 48;

        const int myT = (TOT_TILES - bx + NGEMM_CTAS - 1) / NGEMM_CTAS;
        const int totq = myT * NCHUNK;

        auto issue = [&](int q) {
            if (q >= totq) return;
            const int tile = bx + (q >> 2) * NGEMM_CTAS;
            const int c = q & 3;
            const int m0 = (tile >> 3) * BM;
            const int n0 = (tile & 7) * BN;
            const int k0 = c * BK;
            const uint32_t sb = sbase + (uint32_t)((q & 1) * STAGE_B);
            const __half* srcA = g_Ah + (size_t)m0 * KDIM + k0;
            const __half* srcB = g_Bh + (size_t)n0 * KDIM + k0;
#pragma unroll
            for (int j = 0; j < 8; ++j) {               // A: 2048 uint4
                const int slot = j * 256 + tid;
                const int row  = slot >> 4;
                const int kb   = slot & 15;
                cp_async16(sb + (kb >> 3) * ASUB_B + SW128(row * 128 + (kb & 7) * 16),
                           srcA + (size_t)row * KDIM + kb * 8);
            }
#pragma unroll
            for (int j = 0; j < 12; ++j) {              // B: 3072 uint4
                const int slot = j * 256 + tid;
                const int row  = slot >> 4;
                const int kb   = slot & 15;
                cp_async16(sb + ABUF_B + (kb >> 3) * BSUB_B + SW128(row * 128 + (kb & 7) * 16),
                           srcB + (size_t)row * KDIM + kb * 8);
            }
        };

        float acc[4][6][4];
#pragma unroll
        for (int i = 0; i < 4; i++)
#pragma unroll
            for (int j = 0; j < 6; j++)
#pragma unroll
                for (int q = 0; q < 4; q++) acc[i][j][q] = 0.f;

        issue(0); CP_COMMIT();

        for (int q = 0; q < totq; ++q) {
            issue(q + 1); CP_COMMIT();
            CP_WAIT(1);
            BARG();

            const uint32_t sb = sbase + (uint32_t)((q & 1) * STAGE_B);
            const uint32_t sA = sb;
            const uint32_t sB = sb + ABUF_B;

#pragma unroll
            for (int s = 0; s < 8; ++s) {   // eight k16 steps
                uint32_t ah[4][4];
                {
                    const int arow = (lane & 15);
                    const int akb  = 2 * s + (lane >> 4);      // 0..15
                    const uint32_t asub = (uint32_t)(akb >> 3) * ASUB_B;
#pragma unroll
                    for (int mf = 0; mf < 4; ++mf) {
                        const uint32_t off = asub + SW128((uint32_t)(wm0 + mf * 16 + arow) * 128 + (akb & 7) * 16);
                        ldsm_x4(ah[mf][0], ah[mf][1], ah[mf][2], ah[mf][3], sA + off);
                    }
                }
                uint32_t bh[6][2];
                {
                    const int brow = (lane & 7) + ((lane >> 4) & 1) * 8;
                    const int bkb  = 2 * s + ((lane >> 3) & 1); // 0..15
                    const uint32_t bsub = (uint32_t)(bkb >> 3) * BSUB_B;
#pragma unroll
                    for (int nf16 = 0; nf16 < 3; ++nf16) {
                        const uint32_t off = bsub + SW128((uint32_t)(wn0 + nf16 * 16 + brow) * 128 + (bkb & 7) * 16);
                        ldsm_x4(bh[nf16*2][0], bh[nf16*2][1], bh[nf16*2+1][0], bh[nf16*2+1][1], sB + off);
                    }
                }
#pragma unroll
                for (int mf = 0; mf < 4; ++mf)
#pragma unroll
                    for (int nf = 0; nf < 6; ++nf) {
                        float* C = acc[mf][nf];
                        mma_f16(C[0], C[1], C[2], C[3],
                                ah[mf][0], ah[mf][1], ah[mf][2], ah[mf][3],
                                bh[nf][0], bh[nf][1]);
                    }
            }
            BARG();

            if ((q & 3) == 3) {
                const int tile = bx + (q >> 2) * NGEMM_CTAS;
                const int m0 = (tile >> 3) * BM;
                const int d0 = (tile & 7) * 64;
                float* ep = (float*)(smem + (size_t)((q & 1) * STAGE_B));

#pragma unroll
                for (int q2 = 0; q2 < 4; ++q2) {
                    if (wmh == (q2 >> 1)) {
                        const int g = lane >> 2;
                        const int t4 = lane & 3;
#pragma unroll
                        for (int e = 0; e < 2; ++e) {
                            const int mf = 2 * (q2 & 1) + e;
                            const int lr = e * 16 + g;
#pragma unroll
                            for (int nf = 0; nf < 6; ++nf) {
                                const int col = wn0 + nf * 8 + 2 * t4;
                                float* C = acc[mf][nf];
                                ep[lr * EP_P + col]           = C[0];
                                ep[lr * EP_P + col + 1]       = C[1];
                                ep[(lr + 8) * EP_P + col]     = C[2];
                                ep[(lr + 8) * EP_P + col + 1] = C[3];
                            }
                        }
                    }
                    BARG();
#pragma unroll
                    for (int it = 0; it < 8; ++it) {
                        const int lin = it * 256 + tid;    // 0..2047
                        const int lr = lin >> 6;
                        const int dc = lin & 63;
                        const float u0 = ep[lr * EP_P + 3 * dc];
                        const float u1 = ep[lr * EP_P + 3 * dc + 1];
                        const float u2 = ep[lr * EP_P + 3 * dc + 2];
                        uint2 w;
                        w.x = __float_as_uint(u0);
                        const __half2 p = __floats2half2_rn(u1, u2);
                        w.y = *(const uint32_t*)&p;
                        g_U8[(size_t)(m0 + q2 * 32 + lr) * DDIM + d0 + dc] = w;
                    }
                    BARG();
                }

                __threadfence();
                BARG();
                if (tid == 0) atomicAdd(&g_cnt[tile >> 3], 1);

#pragma unroll
                for (int i = 0; i < 4; i++)
#pragma unroll
                    for (int j = 0; j < 6; j++)
#pragma unroll
                        for (int p = 0; p < 4; p++) acc[i][j][p] = 0.f;
            }
        }
    } else {
        // ================= scan consumer =================
        if (bx >= 128) return;
        const int st = tid - 256;                 // 0..127
        const int ch = bx * 128 + st;             // b*D + d
        const int d = ch & (DDIM - 1);

        const float LOG2E = 1.4426950408889634f;
        const float wcf2 = -wc[d] * LOG2E;
        const float wcr2 = -wc[DDIM + d] * LOG2E;
        const float bf2 = -bias[d] * LOG2E;
        const float br2 = -bias[DDIM + d] * LOG2E;

        const uint32_t ru_base = smem_u32(&s_ru[0][0]);
        const uint32_t rx_base = smem_u32(&s_rx[0][0]);
        const size_t stride = (size_t)BDIM * DDIM;      // 16384

        int seen = 0;                 // monotonic cache of observed completions
        auto wait_tile = [&](int mt) {
            if (mt < seen) return;
            int v = ld_cnt(&g_cnt[mt]);
            while (v < NTILES_N) { __nanosleep(64); v = ld_cnt(&g_cnt[mt]); }
            seen = mt + 1;
        };

#pragma unroll
        for (int g = 0; g < 4; ++g) {
            wait_tile(g);
#pragma unroll
            for (int i = 0; i < 4; ++i) {
                const int l = g * 4 + i;
                cp_async8(ru_base + (uint32_t)((l & (SSTG - 1)) * 128 + st) * 8,
                          g_U8 + (size_t)l * stride + ch);
                cp_async4(rx_base + (uint32_t)((l & (SSTG - 1)) * 128 + st) * 4,
                          x + (size_t)l * stride + ch);
            }
            CP_COMMIT();
        }

        float c = 0.f;
        for (int gi = 0; gi < LDIM / 4; ++gi) {
            CP_WAIT(3);
#pragma unroll
            for (int i = 0; i < 4; ++i) {
                const int l = gi * 4 + i;
                const int slot = l & (SSTG - 1);
                const uint2 w = s_ru[slot][st];
                const float xv = s_rx[slot][st];
                const float u0 = __uint_as_float(w.x);
                const float2 u12 = __half22float2(*(const __half2*)&w.y);

                const float fg = rcpf(1.f + ex2f(fmaf(wcf2, c, fmaf(-LOG2E, u12.x, bf2))));
                const float rg = rcpf(1.f + ex2f(fmaf(wcr2, c, fmaf(-LOG2E, u12.y, br2))));
                c = fmaf(fg, c - u0, u0);
                const float h = fmaf(rg, c - xv, xv);
                out[(size_t)l * stride + ch] = h;
            }
            const int ng = gi + 4;
            if (ng < LDIM / 4) {
                wait_tile(ng);
#pragma unroll
                for (int i = 0; i < 4; ++i) {
                    const int nl = ng * 4 + i;
                    cp_async8(ru_base + (uint32_t)((nl & (SSTG - 1)) * 128 + st) * 8,
                              g_U8 + (size_t)nl * stride + ch);
                    cp_async4(rx_base + (uint32_t)((nl & (SSTG - 1)) * 128 + st) * 4,
                              x + (size_t)nl * stride + ch);
                }
            }
            CP_COMMIT();
        }

        out[(size_t)LDIM * stride + ch] = c;
    }
}

// ---------------------------------------------------------------------------
extern "C" void kernel_launch(void* const* d_in, const int* in_sizes, int n_in,
                              void* d_out, int out_size)
{
    const float* x    = (const float*)d_in[0];   // (L,B,D)
    const float* W    = (const float*)d_in[1];   // (D, 3D)
    const float* wc   = (const float*)d_in[2];   // (2D,)
    const float* bias = (const float*)d_in[3];   // (2D,)
    float* out = (float*)d_out;

    cudaFuncSetAttribute(sru_fused, cudaFuncAttributeMaxDynamicSharedMemorySize, GSMEM);

    convert_all_kernel<<<(MDIM * KDIM / 8) / 256, 256>>>(x, W);   // also resets g_cnt

    sru_fused<<<NGEMM_CTAS, 384, GSMEM>>>(x, wc, bias, out);
}